// round 10
// baseline (speedup 1.0000x reference)
#include <cuda_runtime.h>
#include <cuda_bf16.h>

// ---------------- problem constants ----------------
#define N_SPANS   2000
#define D_SPAN    1220
#define NPAIRS    65536
#define HID       150
#define HPAD      160          // padded hidden dim (zero-padded 150..159)
#define NPHI      189          // 9 bins * 7 genres * 3 speakers
#define NSLOTS    18           // 6 TA + 6 TB(lin) + 6 TB(sq) k-slots
#define KDIM      152          // padded layer-2 K (19 * 8)
#define NGRAN     38           // KDIM/4 granules per table row

// ---------------- scratch (static device memory; no allocs) ----------------
__device__ __align__(256) float    d_Cpart[NSLOTS][N_SPANS * HPAD];
__device__ __align__(256) float    d_TA[N_SPANS * HPAD];     // g[m] @ W1a
__device__ __align__(256) float    d_TB[N_SPANS * HPAD];     // g[a]@W1b + g[a]^2@W1c
__device__ __align__(256) float    d_TPHI[NPHI * HPAD];      // phi @ W1d + b1
__device__ __align__(256) unsigned d_W2t[KDIM * HPAD];       // W2 as tf32 bits, padded

__device__ __forceinline__ unsigned f2tf32(float x) {
    unsigned r;
    asm("cvt.rna.tf32.f32 %0, %1;" : "=r"(r) : "f"(x));
    return r;
}

__device__ __forceinline__ void mma_tf32(float& c0, float& c1, float& c2, float& c3,
                                         unsigned a0, unsigned a1, unsigned a2, unsigned a3,
                                         unsigned b0, unsigned b1)
{
    asm volatile(
        "mma.sync.aligned.m16n8k8.row.col.f32.tf32.tf32.f32 "
        "{%0,%1,%2,%3}, {%4,%5,%6,%7}, {%8,%9}, {%0,%1,%2,%3};\n"
        : "+f"(c0), "+f"(c1), "+f"(c2), "+f"(c3)
        : "r"(a0), "r"(a1), "r"(a2), "r"(a3), "r"(b0), "r"(b1));
}

__device__ __forceinline__ void cpa16(unsigned dst, const void* src, int srcsize) {
    asm volatile("cp.async.ca.shared.global [%0], [%1], 16, %2;\n"
                 :: "r"(dst), "l"(src), "r"(srcsize));
}
__device__ __forceinline__ void cpa8(unsigned dst, const void* src, int srcsize) {
    asm volatile("cp.async.ca.shared.global [%0], [%1], 8, %2;\n"
                 :: "r"(dst), "l"(src), "r"(srcsize));
}
__device__ __forceinline__ void cpa_commit() {
    asm volatile("cp.async.commit_group;\n");
}
__device__ __forceinline__ void cpa_wait0() {
    asm volatile("cp.async.wait_group 0;\n");
}

#define NB_SYNC(id, cnt)   asm volatile("bar.sync %0, %1;"   :: "r"(id), "r"(cnt) : "memory")
#define NB_ARRIVE(id, cnt) asm volatile("bar.arrive %0, %1;" :: "r"(id), "r"(cnt) : "memory")

// =====================================================================
// K_prepphi: fused W2->tf32 conversion (blocks 0..94) and TPHI build
// (blocks 95..283).  Keeps k_pairs as the 4th launch for ncu capture.
// =====================================================================
#define PREP_BLOCKS 95         // 95*256 = 24320 = KDIM*HPAD exactly

__global__ void k_prepphi(const float* __restrict__ W2,
                          const float* __restrict__ de, const float* __restrict__ ge,
                          const float* __restrict__ se, const float* __restrict__ W1,
                          const float* __restrict__ b1)
{
    if (blockIdx.x < PREP_BLOCKS) {
        int idx = blockIdx.x * 256 + threadIdx.x;     // < KDIM*HPAD
        int row = idx / HPAD;
        int j   = idx % HPAD;
        float v = (row < HID && j < HID) ? W2[row * HID + j] : 0.0f;
        d_W2t[idx] = f2tf32(v);
    } else {
        int c = blockIdx.x - PREP_BLOCKS;             // 0..NPHI-1
        int j = threadIdx.x;
        if (j < HPAD) {
            int bin = c / 21;
            int r   = c % 21;
            int gg  = r / 3;
            int ss  = r % 3;
            float v = 0.0f;
            if (j < HID) {
                v = b1[j];
                #pragma unroll
                for (int t = 0; t < 20; ++t) {
                    v += de[bin * 20 + t] * W1[(3660 + t) * HID + j];
                    v += ge[gg  * 20 + t] * W1[(3680 + t) * HID + j];
                    v += se[ss  * 20 + t] * W1[(3700 + t) * HID + j];
                }
            }
            d_TPHI[c * HPAD + j] = v;
        }
    }
}

// =====================================================================
// K1: precompute TA / TB partials with TF32 mma, cp.async staging,
//     single-sync double-buffered chunk pipeline.  (unchanged from R9)
// =====================================================================
#define PRE_ATF_W   (2 * 128 * 36)     // 9216 words
#define PRE_BTF_W   (2 * 32 * 168)     // 10752 words
#define PRE_SMEM_W  (PRE_ATF_W + PRE_BTF_W)
#define PRE_SMEM_B  (PRE_SMEM_W * 4)

__global__ __launch_bounds__(256, 2) void k_precompute(const float* __restrict__ g,
                                                       const float* __restrict__ W1)
{
    extern __shared__ unsigned SP[];
    unsigned* Atf = SP;                 // 2 buffers of [128][36]
    unsigned* Btf = SP + PRE_ATF_W;     // 2 buffers of [32][168]

    const int mtile = blockIdx.x;          // 0..15
    const int slot  = blockIdx.y;          // 0..17
    const int mbase = mtile * 128;
    const int type  = slot / 6;            // 0 TA, 1 TBlin, 2 TBsq
    const int sub   = slot % 6;
    const int kbase = sub * 204;
    const int klen  = (sub == 5) ? 200 : 204;
    const int wrow0 = type * 1220;
    const bool sq   = (type == 2);

    const int tid  = threadIdx.x;
    const int lane = tid & 31;
    const int wid  = tid >> 5;
    const int mwarp = (wid & 1) * 64;
    const int jwarp = (wid >> 1) * 40;
    const int lq = lane >> 2;
    const int lr = lane & 3;

    const int am = tid >> 3;            // A: row group base (m = am + 32*it)
    const int aq = tid & 7;             // A: 16B quad within row
    const int brow = tid >> 3;          // B: k-row 0..31
    const int bj   = tid & 7;           // B: j2 = bj + 8*s

    unsigned a_smem_base = (unsigned)__cvta_generic_to_shared(Atf);
    unsigned b_smem_base = (unsigned)__cvta_generic_to_shared(Btf);

    float c[4][5][4];
    #pragma unroll
    for (int pt = 0; pt < 4; ++pt)
        #pragma unroll
        for (int nt = 0; nt < 5; ++nt)
            #pragma unroll
            for (int i = 0; i < 4; ++i) c[pt][nt][i] = 0.0f;

    auto stageA = [&](int ch, int bsel) {
        unsigned abase = a_smem_base + bsel * (128 * 36 * 4);
        if (!sq) {
            #pragma unroll
            for (int it = 0; it < 4; ++it) {
                int m  = am + it * 32;
                int kk = ch * 32 + aq * 4;
                int ok = ((mbase + m) < N_SPANS && kk < klen) ? 16 : 0;
                const float* src = g + (size_t)(mbase + (ok ? m : 0)) * D_SPAN
                                     + (ok ? (kbase + kk) : 0);
                cpa16(abase + (m * 36 + aq * 4) * 4, src, ok);
            }
        } else {
            unsigned* ab = (unsigned*)Atf + bsel * (128 * 36);
            #pragma unroll
            for (int it = 0; it < 4; ++it) {
                int m  = am + it * 32;
                int kk = ch * 32 + aq * 4;
                float4 v = make_float4(0.f, 0.f, 0.f, 0.f);
                if ((mbase + m) < N_SPANS && kk < klen)
                    v = *(const float4*)(g + (size_t)(mbase + m) * D_SPAN + kbase + kk);
                uint4 o;
                o.x = f2tf32(v.x * v.x);
                o.y = f2tf32(v.y * v.y);
                o.z = f2tf32(v.z * v.z);
                o.w = f2tf32(v.w * v.w);
                *(uint4*)(ab + m * 36 + aq * 4) = o;
            }
        }
    };
    auto stageB = [&](int ch, int bsel) {
        unsigned bbase = b_smem_base + bsel * (32 * 168 * 4);
        int kk = ch * 32 + brow;
        const float* rowp = W1 + (size_t)(wrow0 + kbase + ((kk < klen) ? kk : 0)) * HID;
        #pragma unroll
        for (int s = 0; s < 10; ++s) {
            int j2 = bj + 8 * s;        // 0..79
            int ok = (kk < klen && j2 < 75) ? 8 : 0;
            cpa8(bbase + (brow * 168 + j2 * 2) * 4, rowp + (ok ? j2 * 2 : 0), ok);
        }
    };

    stageA(0, 0);
    stageB(0, 0);
    cpa_commit();

    for (int ch = 0; ch < 7; ++ch) {            // 7 chunks cover klen <= 224
        const int buf = ch & 1;
        cpa_wait0();
        __syncthreads();
        if (ch < 6) {
            stageA(ch + 1, buf ^ 1);
            stageB(ch + 1, buf ^ 1);
            cpa_commit();
        }
        const unsigned* Ab = (const unsigned*)Atf + buf * (128 * 36);
        const unsigned* Bb = (const unsigned*)Btf + buf * (32 * 168);
        #pragma unroll
        for (int ks = 0; ks < 4; ++ks) {
            const int kcs = ks * 8;
            unsigned bfr[5][2];
            #pragma unroll
            for (int nt = 0; nt < 5; ++nt) {
                int j = jwarp + nt * 8 + lq;
                bfr[nt][0] = Bb[(kcs + lr)     * 168 + j];
                bfr[nt][1] = Bb[(kcs + lr + 4) * 168 + j];
            }
            #pragma unroll
            for (int pt = 0; pt < 4; ++pt) {
                int m = mwarp + pt * 16 + lq;
                unsigned a0 = Ab[m       * 36 + kcs + lr];
                unsigned a1 = Ab[(m + 8) * 36 + kcs + lr];
                unsigned a2 = Ab[m       * 36 + kcs + lr + 4];
                unsigned a3 = Ab[(m + 8) * 36 + kcs + lr + 4];
                #pragma unroll
                for (int nt = 0; nt < 5; ++nt)
                    mma_tf32(c[pt][nt][0], c[pt][nt][1], c[pt][nt][2], c[pt][nt][3],
                             a0, a1, a2, a3, bfr[nt][0], bfr[nt][1]);
            }
        }
    }

    float* dst = d_Cpart[slot];
    #pragma unroll
    for (int pt = 0; pt < 4; ++pt) {
        int m0 = mbase + mwarp + pt * 16 + lq;
        #pragma unroll
        for (int nt = 0; nt < 5; ++nt) {
            int j = jwarp + nt * 8 + 2 * lr;
            if (m0 < N_SPANS)
                *(float2*)(dst + (size_t)m0 * HPAD + j) = make_float2(c[pt][nt][0], c[pt][nt][1]);
            if (m0 + 8 < N_SPANS)
                *(float2*)(dst + (size_t)(m0 + 8) * HPAD + j) = make_float2(c[pt][nt][2], c[pt][nt][3]);
        }
    }
}

// =====================================================================
// K2: reduce k-split partials into TA / TB (float2)
// =====================================================================
__global__ void k_reduce()
{
    int idx = blockIdx.x * blockDim.x + threadIdx.x;
    if (idx < N_SPANS * HPAD / 2) {
        float2 ta = make_float2(0.f, 0.f);
        float2 tb = ta;
        #pragma unroll
        for (int s = 0; s < 6; ++s) {
            float2 v = ((const float2*)d_Cpart[s])[idx];
            ta.x += v.x; ta.y += v.y;
        }
        #pragma unroll
        for (int s = 6; s < 18; ++s) {
            float2 v = ((const float2*)d_Cpart[s])[idx];
            tb.x += v.x; tb.y += v.y;
        }
        ((float2*)d_TA)[idx] = ta;
        ((float2*)d_TB)[idx] = tb;
    }
}

// =====================================================================
// K3: fused pair kernel, WARP-SPECIALIZED producer/consumer.
//   512 blocks x 320 threads: warps 0..7 consume (LDS+MMA only),
//   warps 8..9 produce (W2 cp.async + table gather LDG/STS).
//   Double-buffered chunks; named barriers: full0=1 full1=2 empty0=3 empty1=4.
// =====================================================================
#define KP_HB_W   (2 * 128 * 36)       // 9216 words
#define KP_WB_W   (2 * 32 * 168)       // 10752 words
#define KP_OFF_W3 (KP_HB_W + KP_WB_W)  // 19968
#define KP_OFF_B2 (KP_OFF_W3 + HPAD)
#define KP_OFF_SB (KP_OFF_B2 + HPAD)
#define KP_OFF_M  (KP_OFF_SB + 128)
#define KP_OFF_A  (KP_OFF_M + 128)
#define KP_OFF_C  (KP_OFF_A + 128)
#define KP_SMEM_W (KP_OFF_C + 128)
#define KP_SMEM_B (KP_SMEM_W * 4)
#define NTHR      320

__global__ __launch_bounds__(NTHR, 2) void k_pairs(
    const float* __restrict__ s_m, const int* __restrict__ mids,
    const int* __restrict__ aids, const int* __restrict__ dist,
    const int* __restrict__ genre, const int* __restrict__ spk,
    const float* __restrict__ W3, const float* __restrict__ b2,
    const float* __restrict__ b3, float* __restrict__ out)
{
    extern __shared__ unsigned SU[];
    unsigned* Hb  = SU;                       // 2 x [128][36]
    unsigned* Wb  = SU + KP_HB_W;             // 2 x [32][168]
    float*    W3s = (float*)(SU + KP_OFF_W3);
    float*    b2s = (float*)(SU + KP_OFF_B2);
    float*    sbS = (float*)(SU + KP_OFF_SB);
    int*      mS  = (int*)(SU + KP_OFF_M);
    int*      aS  = (int*)(SU + KP_OFF_A);
    int*      cS  = (int*)(SU + KP_OFF_C);
    float*    red = (float*)(Wb + 32 * 168);  // alias Wb buffer 1 (free at epilogue)

    const int tid   = threadIdx.x;
    const int lane  = tid & 31;
    const int wid   = tid >> 5;
    const int pbase = blockIdx.x * 128;

    // ---- per-pair metadata -> smem ----
    if (tid < 128) {
        int p = pbase + tid;
        int m = mids[p];
        int a = aids[p];
        mS[tid] = m;
        aS[tid] = a;
        int d = dist[p];
        int bin;
        if      (d >= 64) bin = 8;
        else if (d >= 32) bin = 7;
        else if (d >= 16) bin = 6;
        else if (d >= 8)  bin = 5;
        else if (d >= 5)  bin = 4;
        else              bin = (d >= 1) ? (d - 1) : 0;
        cS[tid] = (bin * 7 + genre[p]) * 3 + spk[p];
        sbS[tid] = s_m[m] + s_m[a];
    }
    if (tid < HPAD) {
        float w3v = 0.0f, b2v = 0.0f;
        if (tid < HID) { w3v = W3[tid]; b2v = b2[tid]; }
        W3s[tid] = w3v;
        b2s[tid] = b2v;
    }
    __syncthreads();

    if (wid < 8) {
        // ================= CONSUMERS: pure LDS + MMA =================
        const int pwarp = (wid & 1) * 64;
        const int jg    = wid >> 1;
        const int jwarp = jg * 40;
        const int lq = lane >> 2;
        const int lr = lane & 3;

        float c[4][5][4];
        #pragma unroll
        for (int pt = 0; pt < 4; ++pt)
            #pragma unroll
            for (int nt = 0; nt < 5; ++nt)
                #pragma unroll
                for (int i = 0; i < 4; ++i) c[pt][nt][i] = 0.0f;

        for (int ch = 0; ch < 5; ++ch) {
            const int buf = ch & 1;
            NB_SYNC(1 + buf, NTHR);                 // wait full[buf]
            const unsigned* hb = Hb + buf * (128 * 36);
            const unsigned* wb = Wb + buf * (32 * 168);
            const int nks = (ch == 4) ? 3 : 4;
            for (int ks = 0; ks < nks; ++ks) {
                const int kcs = ks * 8;
                unsigned bfr[5][2];
                #pragma unroll
                for (int nt = 0; nt < 5; ++nt) {
                    int j = jwarp + nt * 8 + lq;
                    bfr[nt][0] = wb[(kcs + lr)     * 168 + j];
                    bfr[nt][1] = wb[(kcs + lr + 4) * 168 + j];
                }
                #pragma unroll
                for (int pt = 0; pt < 4; ++pt) {
                    int pp = pwarp + pt * 16 + lq;
                    unsigned a0 = hb[pp       * 36 + kcs + lr];
                    unsigned a1 = hb[(pp + 8) * 36 + kcs + lr];
                    unsigned a2 = hb[pp       * 36 + kcs + lr + 4];
                    unsigned a3 = hb[(pp + 8) * 36 + kcs + lr + 4];
                    #pragma unroll
                    for (int nt = 0; nt < 5; ++nt)
                        mma_tf32(c[pt][nt][0], c[pt][nt][1], c[pt][nt][2], c[pt][nt][3],
                                 a0, a1, a2, a3, bfr[nt][0], bfr[nt][1]);
                }
            }
            if (ch < 3) NB_ARRIVE(3 + buf, NTHR);   // free buf for producers
        }

        // ---- epilogue: relu(+b2) dot W3 ----
        float sp[4][2];
        #pragma unroll
        for (int pt = 0; pt < 4; ++pt) { sp[pt][0] = 0.0f; sp[pt][1] = 0.0f; }

        #pragma unroll
        for (int nt = 0; nt < 5; ++nt) {
            int j = jwarp + nt * 8 + 2 * lr;
            float w3a = W3s[j],     b2a = b2s[j];
            float w3b = W3s[j + 1], b2b = b2s[j + 1];
            #pragma unroll
            for (int pt = 0; pt < 4; ++pt) {
                sp[pt][0] += fmaxf(c[pt][nt][0] + b2a, 0.0f) * w3a;
                sp[pt][0] += fmaxf(c[pt][nt][1] + b2b, 0.0f) * w3b;
                sp[pt][1] += fmaxf(c[pt][nt][2] + b2a, 0.0f) * w3a;
                sp[pt][1] += fmaxf(c[pt][nt][3] + b2b, 0.0f) * w3b;
            }
        }
        #pragma unroll
        for (int pt = 0; pt < 4; ++pt) {
            #pragma unroll
            for (int h = 0; h < 2; ++h) {
                sp[pt][h] += __shfl_xor_sync(0xffffffffu, sp[pt][h], 1);
                sp[pt][h] += __shfl_xor_sync(0xffffffffu, sp[pt][h], 2);
            }
        }

        if (lr == 0) {
            #pragma unroll
            for (int pt = 0; pt < 4; ++pt) {
                int pp = pwarp + pt * 16 + lq;
                red[jg * 128 + pp]     = sp[pt][0];
                red[jg * 128 + pp + 8] = sp[pt][1];
            }
        }
        NB_SYNC(5, 256);                            // consumers only

        if (tid < 128) {
            float t = red[tid] + red[128 + tid] + red[256 + tid] + red[384 + tid];
            out[pbase + tid] = t + b3[0] + sbS[tid];
        }
    } else {
        // ================= PRODUCERS: stage W2 + gather =================
        const int ptid = tid - 256;                 // 0..63
        const int kseg = ptid & 7;                  // 16B granule in chunk
        const int pr   = ptid >> 3;                 // 0..7
        const float4* TA4 = (const float4*)d_TA;
        const float4* TB4 = (const float4*)d_TB;
        const float4* TP4 = (const float4*)d_TPHI;
        unsigned w_smem_base = (unsigned)__cvta_generic_to_shared(Wb);

        for (int ch = 0; ch < 5; ++ch) {
            const int buf = ch & 1;
            if (ch >= 2) NB_SYNC(3 + buf, NTHR);    // wait empty[buf]

            // W2 chunk via cp.async
            {
                unsigned wb = w_smem_base + buf * (32 * 168 * 4);
                const int rows = (ch == 4) ? 24 : 32;
                for (int i4 = ptid; i4 < rows * 40; i4 += 64) {
                    int row = i4 / 40;
                    int j4  = i4 - row * 40;
                    cpa16(wb + (row * 168 + j4 * 4) * 4,
                          d_W2t + (ch * 32 + row) * HPAD + j4 * 4, 16);
                }
                cpa_commit();
            }

            // gather: 1024 slots / 64 threads, batched 8 pairs at a time
            {
                unsigned* hb = Hb + buf * (128 * 36);
                const int kk = ch * 8 + kseg;       // 0..39 (38,39 rows unread)
                #pragma unroll
                for (int gblk = 0; gblk < 2; ++gblk) {
                    float4 va[8], vb4[8], vc[8];
                    #pragma unroll
                    for (int u = 0; u < 8; ++u) {
                        int p = pr + (gblk * 8 + u) * 8;
                        va[u]  = TA4[mS[p] * 40 + kk];
                        vb4[u] = TB4[aS[p] * 40 + kk];
                        vc[u]  = TP4[cS[p] * 40 + kk];
                    }
                    #pragma unroll
                    for (int u = 0; u < 8; ++u) {
                        int p = pr + (gblk * 8 + u) * 8;
                        uint4 o;
                        o.x = __float_as_uint(fmaxf(va[u].x + vb4[u].x + vc[u].x, 0.0f));
                        o.y = __float_as_uint(fmaxf(va[u].y + vb4[u].y + vc[u].y, 0.0f));
                        o.z = __float_as_uint(fmaxf(va[u].z + vb4[u].z + vc[u].z, 0.0f));
                        o.w = __float_as_uint(fmaxf(va[u].w + vb4[u].w + vc[u].w, 0.0f));
                        *(uint4*)(hb + p * 36 + kseg * 4) = o;
                    }
                }
            }

            cpa_wait0();                            // W2 cp.asyncs landed
            NB_ARRIVE(1 + buf, NTHR);               // signal full[buf]
        }
    }
}

// =====================================================================
// launch
// =====================================================================
extern "C" void kernel_launch(void* const* d_in, const int* in_sizes, int n_in,
                              void* d_out, int out_size)
{
    const float* g    = (const float*)d_in[0];
    const float* s_m  = (const float*)d_in[1];
    const int*   mids = (const int*)d_in[2];
    const int*   aids = (const int*)d_in[3];
    const int*   dist = (const int*)d_in[4];
    const int*   genr = (const int*)d_in[5];
    const int*   spk  = (const int*)d_in[6];
    const float* de   = (const float*)d_in[7];
    const float* ge   = (const float*)d_in[8];
    const float* se   = (const float*)d_in[9];
    const float* W1   = (const float*)d_in[10];
    const float* b1   = (const float*)d_in[11];
    const float* W2   = (const float*)d_in[12];
    const float* b2   = (const float*)d_in[13];
    const float* W3   = (const float*)d_in[14];
    const float* b3   = (const float*)d_in[15];
    float* out = (float*)d_out;

    static int attr_done = 0;
    if (!attr_done) {
        cudaFuncSetAttribute(k_precompute, cudaFuncAttributeMaxDynamicSharedMemorySize, PRE_SMEM_B);
        cudaFuncSetAttribute(k_pairs, cudaFuncAttributeMaxDynamicSharedMemorySize, KP_SMEM_B);
        attr_done = 1;
    }

    k_prepphi<<<PREP_BLOCKS + NPHI, 256>>>(W2, de, ge, se, W1, b1);
    k_precompute<<<dim3(16, NSLOTS), 256, PRE_SMEM_B>>>(g, W1);
    k_reduce<<<(N_SPANS * HPAD / 2 + 255) / 256, 256>>>();
    k_pairs<<<NPAIRS / 128, NTHR, KP_SMEM_B>>>(s_m, mids, aids, dist, genr, spk,
                                               W3, b2, b3, out);
}

// round 11
// speedup vs baseline: 1.0549x; 1.0549x over previous
#include <cuda_runtime.h>
#include <cuda_bf16.h>

// ---------------- problem constants ----------------
#define N_SPANS   2000
#define D_SPAN    1220
#define NPAIRS    65536
#define HID       150
#define HPAD      160          // padded hidden dim (zero-padded 150..159)
#define NPHI      189          // 9 bins * 7 genres * 3 speakers
#define NSLOTS    18           // 6 TA + 6 TB(lin) + 6 TB(sq) k-slots
#define KDIM      152          // padded layer-2 K (19 * 8)
#define NGRAN     38           // KDIM/4 granules per table row

// ---------------- scratch (static device memory; no allocs) ----------------
__device__ __align__(256) float    d_Cpart[NSLOTS][N_SPANS * HPAD];
__device__ __align__(256) float    d_TA[N_SPANS * HPAD];     // g[m] @ W1a
__device__ __align__(256) float    d_TB[N_SPANS * HPAD];     // g[a]@W1b + g[a]^2@W1c
__device__ __align__(256) float    d_TPHI[NPHI * HPAD];      // phi @ W1d + b1
__device__ __align__(256) unsigned d_W2t[KDIM * HPAD];       // W2 as tf32 bits, padded

__device__ __forceinline__ unsigned f2tf32(float x) {
    unsigned r;
    asm("cvt.rna.tf32.f32 %0, %1;" : "=r"(r) : "f"(x));
    return r;
}

__device__ __forceinline__ void mma_tf32(float& c0, float& c1, float& c2, float& c3,
                                         unsigned a0, unsigned a1, unsigned a2, unsigned a3,
                                         unsigned b0, unsigned b1)
{
    asm volatile(
        "mma.sync.aligned.m16n8k8.row.col.f32.tf32.tf32.f32 "
        "{%0,%1,%2,%3}, {%4,%5,%6,%7}, {%8,%9}, {%0,%1,%2,%3};\n"
        : "+f"(c0), "+f"(c1), "+f"(c2), "+f"(c3)
        : "r"(a0), "r"(a1), "r"(a2), "r"(a3), "r"(b0), "r"(b1));
}

__device__ __forceinline__ void cpa16(unsigned dst, const void* src, int srcsize) {
    asm volatile("cp.async.ca.shared.global [%0], [%1], 16, %2;\n"
                 :: "r"(dst), "l"(src), "r"(srcsize));
}
__device__ __forceinline__ void cpa8(unsigned dst, const void* src, int srcsize) {
    asm volatile("cp.async.ca.shared.global [%0], [%1], 8, %2;\n"
                 :: "r"(dst), "l"(src), "r"(srcsize));
}
__device__ __forceinline__ void cpa_commit() {
    asm volatile("cp.async.commit_group;\n");
}
__device__ __forceinline__ void cpa_wait0() {
    asm volatile("cp.async.wait_group 0;\n");
}

#define NB_SYNC(id, cnt)   asm volatile("bar.sync %0, %1;"   :: "r"(id), "r"(cnt) : "memory")
#define NB_ARRIVE(id, cnt) asm volatile("bar.arrive %0, %1;" :: "r"(id), "r"(cnt) : "memory")

// =====================================================================
// K_prepphi: fused W2->tf32 conversion (blocks 0..94) and TPHI build
// (blocks 95..283).  Keeps k_pairs as the 4th launch for ncu capture.
// =====================================================================
#define PREP_BLOCKS 95         // 95*256 = 24320 = KDIM*HPAD exactly

__global__ void k_prepphi(const float* __restrict__ W2,
                          const float* __restrict__ de, const float* __restrict__ ge,
                          const float* __restrict__ se, const float* __restrict__ W1,
                          const float* __restrict__ b1)
{
    if (blockIdx.x < PREP_BLOCKS) {
        int idx = blockIdx.x * 256 + threadIdx.x;     // < KDIM*HPAD
        int row = idx / HPAD;
        int j   = idx % HPAD;
        float v = (row < HID && j < HID) ? W2[row * HID + j] : 0.0f;
        d_W2t[idx] = f2tf32(v);
    } else {
        int c = blockIdx.x - PREP_BLOCKS;             // 0..NPHI-1
        int j = threadIdx.x;
        if (j < HPAD) {
            int bin = c / 21;
            int r   = c % 21;
            int gg  = r / 3;
            int ss  = r % 3;
            float v = 0.0f;
            if (j < HID) {
                v = b1[j];
                #pragma unroll
                for (int t = 0; t < 20; ++t) {
                    v += de[bin * 20 + t] * W1[(3660 + t) * HID + j];
                    v += ge[gg  * 20 + t] * W1[(3680 + t) * HID + j];
                    v += se[ss  * 20 + t] * W1[(3700 + t) * HID + j];
                }
            }
            d_TPHI[c * HPAD + j] = v;
        }
    }
}

// =====================================================================
// K1: precompute TA / TB partials with TF32 mma, cp.async staging,
//     single-sync double-buffered chunk pipeline.  (unchanged)
// =====================================================================
#define PRE_ATF_W   (2 * 128 * 36)     // 9216 words
#define PRE_BTF_W   (2 * 32 * 168)     // 10752 words
#define PRE_SMEM_W  (PRE_ATF_W + PRE_BTF_W)
#define PRE_SMEM_B  (PRE_SMEM_W * 4)

__global__ __launch_bounds__(256, 2) void k_precompute(const float* __restrict__ g,
                                                       const float* __restrict__ W1)
{
    extern __shared__ unsigned SP[];
    unsigned* Atf = SP;                 // 2 buffers of [128][36]
    unsigned* Btf = SP + PRE_ATF_W;     // 2 buffers of [32][168]

    const int mtile = blockIdx.x;          // 0..15
    const int slot  = blockIdx.y;          // 0..17
    const int mbase = mtile * 128;
    const int type  = slot / 6;            // 0 TA, 1 TBlin, 2 TBsq
    const int sub   = slot % 6;
    const int kbase = sub * 204;
    const int klen  = (sub == 5) ? 200 : 204;
    const int wrow0 = type * 1220;
    const bool sq   = (type == 2);

    const int tid  = threadIdx.x;
    const int lane = tid & 31;
    const int wid  = tid >> 5;
    const int mwarp = (wid & 1) * 64;
    const int jwarp = (wid >> 1) * 40;
    const int lq = lane >> 2;
    const int lr = lane & 3;

    const int am = tid >> 3;            // A: row group base (m = am + 32*it)
    const int aq = tid & 7;             // A: 16B quad within row
    const int brow = tid >> 3;          // B: k-row 0..31
    const int bj   = tid & 7;           // B: j2 = bj + 8*s

    unsigned a_smem_base = (unsigned)__cvta_generic_to_shared(Atf);
    unsigned b_smem_base = (unsigned)__cvta_generic_to_shared(Btf);

    float c[4][5][4];
    #pragma unroll
    for (int pt = 0; pt < 4; ++pt)
        #pragma unroll
        for (int nt = 0; nt < 5; ++nt)
            #pragma unroll
            for (int i = 0; i < 4; ++i) c[pt][nt][i] = 0.0f;

    auto stageA = [&](int ch, int bsel) {
        unsigned abase = a_smem_base + bsel * (128 * 36 * 4);
        if (!sq) {
            #pragma unroll
            for (int it = 0; it < 4; ++it) {
                int m  = am + it * 32;
                int kk = ch * 32 + aq * 4;
                int ok = ((mbase + m) < N_SPANS && kk < klen) ? 16 : 0;
                const float* src = g + (size_t)(mbase + (ok ? m : 0)) * D_SPAN
                                     + (ok ? (kbase + kk) : 0);
                cpa16(abase + (m * 36 + aq * 4) * 4, src, ok);
            }
        } else {
            unsigned* ab = (unsigned*)Atf + bsel * (128 * 36);
            #pragma unroll
            for (int it = 0; it < 4; ++it) {
                int m  = am + it * 32;
                int kk = ch * 32 + aq * 4;
                float4 v = make_float4(0.f, 0.f, 0.f, 0.f);
                if ((mbase + m) < N_SPANS && kk < klen)
                    v = *(const float4*)(g + (size_t)(mbase + m) * D_SPAN + kbase + kk);
                uint4 o;
                o.x = f2tf32(v.x * v.x);
                o.y = f2tf32(v.y * v.y);
                o.z = f2tf32(v.z * v.z);
                o.w = f2tf32(v.w * v.w);
                *(uint4*)(ab + m * 36 + aq * 4) = o;
            }
        }
    };
    auto stageB = [&](int ch, int bsel) {
        unsigned bbase = b_smem_base + bsel * (32 * 168 * 4);
        int kk = ch * 32 + brow;
        const float* rowp = W1 + (size_t)(wrow0 + kbase + ((kk < klen) ? kk : 0)) * HID;
        #pragma unroll
        for (int s = 0; s < 10; ++s) {
            int j2 = bj + 8 * s;        // 0..79
            int ok = (kk < klen && j2 < 75) ? 8 : 0;
            cpa8(bbase + (brow * 168 + j2 * 2) * 4, rowp + (ok ? j2 * 2 : 0), ok);
        }
    };

    stageA(0, 0);
    stageB(0, 0);
    cpa_commit();

    for (int ch = 0; ch < 7; ++ch) {            // 7 chunks cover klen <= 224
        const int buf = ch & 1;
        cpa_wait0();
        __syncthreads();
        if (ch < 6) {
            stageA(ch + 1, buf ^ 1);
            stageB(ch + 1, buf ^ 1);
            cpa_commit();
        }
        const unsigned* Ab = (const unsigned*)Atf + buf * (128 * 36);
        const unsigned* Bb = (const unsigned*)Btf + buf * (32 * 168);
        #pragma unroll
        for (int ks = 0; ks < 4; ++ks) {
            const int kcs = ks * 8;
            unsigned bfr[5][2];
            #pragma unroll
            for (int nt = 0; nt < 5; ++nt) {
                int j = jwarp + nt * 8 + lq;
                bfr[nt][0] = Bb[(kcs + lr)     * 168 + j];
                bfr[nt][1] = Bb[(kcs + lr + 4) * 168 + j];
            }
            #pragma unroll
            for (int pt = 0; pt < 4; ++pt) {
                int m = mwarp + pt * 16 + lq;
                unsigned a0 = Ab[m       * 36 + kcs + lr];
                unsigned a1 = Ab[(m + 8) * 36 + kcs + lr];
                unsigned a2 = Ab[m       * 36 + kcs + lr + 4];
                unsigned a3 = Ab[(m + 8) * 36 + kcs + lr + 4];
                #pragma unroll
                for (int nt = 0; nt < 5; ++nt)
                    mma_tf32(c[pt][nt][0], c[pt][nt][1], c[pt][nt][2], c[pt][nt][3],
                             a0, a1, a2, a3, bfr[nt][0], bfr[nt][1]);
            }
        }
    }

    float* dst = d_Cpart[slot];
    #pragma unroll
    for (int pt = 0; pt < 4; ++pt) {
        int m0 = mbase + mwarp + pt * 16 + lq;
        #pragma unroll
        for (int nt = 0; nt < 5; ++nt) {
            int j = jwarp + nt * 8 + 2 * lr;
            if (m0 < N_SPANS)
                *(float2*)(dst + (size_t)m0 * HPAD + j) = make_float2(c[pt][nt][0], c[pt][nt][1]);
            if (m0 + 8 < N_SPANS)
                *(float2*)(dst + (size_t)(m0 + 8) * HPAD + j) = make_float2(c[pt][nt][2], c[pt][nt][3]);
        }
    }
}

// =====================================================================
// K2: reduce k-split partials into TA / TB (float2)
// =====================================================================
__global__ void k_reduce()
{
    int idx = blockIdx.x * blockDim.x + threadIdx.x;
    if (idx < N_SPANS * HPAD / 2) {
        float2 ta = make_float2(0.f, 0.f);
        float2 tb = ta;
        #pragma unroll
        for (int s = 0; s < 6; ++s) {
            float2 v = ((const float2*)d_Cpart[s])[idx];
            ta.x += v.x; ta.y += v.y;
        }
        #pragma unroll
        for (int s = 6; s < 18; ++s) {
            float2 v = ((const float2*)d_Cpart[s])[idx];
            tb.x += v.x; tb.y += v.y;
        }
        ((float2*)d_TA)[idx] = ta;
        ((float2*)d_TB)[idx] = tb;
    }
}

// =====================================================================
// K3: fused pair kernel, WARP-SPECIALIZED producer/consumer.
//   512 blocks x 384 threads, launch_bounds(384, 1): full register
//   budget (no spills — the R10 failure mode).
//   Warps 0..7 consume (LDS+MMA only); warps 8..11 produce
//   (W2 cp.async + table gather LDG/STS, one chunk ahead).
//   Named barriers: full0=1 full1=2 empty0=3 empty1=4; counts=384.
// =====================================================================
#define KP_HB_W   (2 * 128 * 36)       // 9216 words
#define KP_WB_W   (2 * 32 * 168)       // 10752 words
#define KP_OFF_W3 (KP_HB_W + KP_WB_W)  // 19968
#define KP_OFF_B2 (KP_OFF_W3 + HPAD)
#define KP_OFF_SB (KP_OFF_B2 + HPAD)
#define KP_OFF_M  (KP_OFF_SB + 128)
#define KP_OFF_A  (KP_OFF_M + 128)
#define KP_OFF_C  (KP_OFF_A + 128)
#define KP_SMEM_W (KP_OFF_C + 128)
#define KP_SMEM_B (KP_SMEM_W * 4)
#define NTHR      384

__global__ __launch_bounds__(NTHR, 1) void k_pairs(
    const float* __restrict__ s_m, const int* __restrict__ mids,
    const int* __restrict__ aids, const int* __restrict__ dist,
    const int* __restrict__ genre, const int* __restrict__ spk,
    const float* __restrict__ W3, const float* __restrict__ b2,
    const float* __restrict__ b3, float* __restrict__ out)
{
    extern __shared__ unsigned SU[];
    unsigned* Hb  = SU;                       // 2 x [128][36]
    unsigned* Wb  = SU + KP_HB_W;             // 2 x [32][168]
    float*    W3s = (float*)(SU + KP_OFF_W3);
    float*    b2s = (float*)(SU + KP_OFF_B2);
    float*    sbS = (float*)(SU + KP_OFF_SB);
    int*      mS  = (int*)(SU + KP_OFF_M);
    int*      aS  = (int*)(SU + KP_OFF_A);
    int*      cS  = (int*)(SU + KP_OFF_C);
    float*    red = (float*)(Wb + 32 * 168);  // alias Wb buffer 1 (free at epilogue)

    const int tid   = threadIdx.x;
    const int lane  = tid & 31;
    const int wid   = tid >> 5;
    const int pbase = blockIdx.x * 128;

    // ---- per-pair metadata -> smem ----
    if (tid < 128) {
        int p = pbase + tid;
        int m = mids[p];
        int a = aids[p];
        mS[tid] = m;
        aS[tid] = a;
        int d = dist[p];
        int bin;
        if      (d >= 64) bin = 8;
        else if (d >= 32) bin = 7;
        else if (d >= 16) bin = 6;
        else if (d >= 8)  bin = 5;
        else if (d >= 5)  bin = 4;
        else              bin = (d >= 1) ? (d - 1) : 0;
        cS[tid] = (bin * 7 + genre[p]) * 3 + spk[p];
        sbS[tid] = s_m[m] + s_m[a];
    }
    if (tid < HPAD) {
        float w3v = 0.0f, b2v = 0.0f;
        if (tid < HID) { w3v = W3[tid]; b2v = b2[tid]; }
        W3s[tid] = w3v;
        b2s[tid] = b2v;
    }
    __syncthreads();

    if (wid < 8) {
        // ================= CONSUMERS: pure LDS + MMA =================
        const int pwarp = (wid & 1) * 64;
        const int jg    = wid >> 1;
        const int jwarp = jg * 40;
        const int lq = lane >> 2;
        const int lr = lane & 3;

        float c[4][5][4];
        #pragma unroll
        for (int pt = 0; pt < 4; ++pt)
            #pragma unroll
            for (int nt = 0; nt < 5; ++nt)
                #pragma unroll
                for (int i = 0; i < 4; ++i) c[pt][nt][i] = 0.0f;

        for (int ch = 0; ch < 5; ++ch) {
            const int buf = ch & 1;
            NB_SYNC(1 + buf, NTHR);                 // wait full[buf]
            const unsigned* hb = Hb + buf * (128 * 36);
            const unsigned* wb = Wb + buf * (32 * 168);
            const int nks = (ch == 4) ? 3 : 4;
            for (int ks = 0; ks < nks; ++ks) {
                const int kcs = ks * 8;
                unsigned bfr[5][2];
                #pragma unroll
                for (int nt = 0; nt < 5; ++nt) {
                    int j = jwarp + nt * 8 + lq;
                    bfr[nt][0] = wb[(kcs + lr)     * 168 + j];
                    bfr[nt][1] = wb[(kcs + lr + 4) * 168 + j];
                }
                #pragma unroll
                for (int pt = 0; pt < 4; ++pt) {
                    int pp = pwarp + pt * 16 + lq;
                    unsigned a0 = hb[pp       * 36 + kcs + lr];
                    unsigned a1 = hb[(pp + 8) * 36 + kcs + lr];
                    unsigned a2 = hb[pp       * 36 + kcs + lr + 4];
                    unsigned a3 = hb[(pp + 8) * 36 + kcs + lr + 4];
                    #pragma unroll
                    for (int nt = 0; nt < 5; ++nt)
                        mma_tf32(c[pt][nt][0], c[pt][nt][1], c[pt][nt][2], c[pt][nt][3],
                                 a0, a1, a2, a3, bfr[nt][0], bfr[nt][1]);
                }
            }
            if (ch < 3) NB_ARRIVE(3 + buf, NTHR);   // free buf for producers
        }

        // ---- epilogue: relu(+b2) dot W3 ----
        float sp[4][2];
        #pragma unroll
        for (int pt = 0; pt < 4; ++pt) { sp[pt][0] = 0.0f; sp[pt][1] = 0.0f; }

        #pragma unroll
        for (int nt = 0; nt < 5; ++nt) {
            int j = jwarp + nt * 8 + 2 * lr;
            float w3a = W3s[j],     b2a = b2s[j];
            float w3b = W3s[j + 1], b2b = b2s[j + 1];
            #pragma unroll
            for (int pt = 0; pt < 4; ++pt) {
                sp[pt][0] += fmaxf(c[pt][nt][0] + b2a, 0.0f) * w3a;
                sp[pt][0] += fmaxf(c[pt][nt][1] + b2b, 0.0f) * w3b;
                sp[pt][1] += fmaxf(c[pt][nt][2] + b2a, 0.0f) * w3a;
                sp[pt][1] += fmaxf(c[pt][nt][3] + b2b, 0.0f) * w3b;
            }
        }
        #pragma unroll
        for (int pt = 0; pt < 4; ++pt) {
            #pragma unroll
            for (int h = 0; h < 2; ++h) {
                sp[pt][h] += __shfl_xor_sync(0xffffffffu, sp[pt][h], 1);
                sp[pt][h] += __shfl_xor_sync(0xffffffffu, sp[pt][h], 2);
            }
        }

        if (lr == 0) {
            #pragma unroll
            for (int pt = 0; pt < 4; ++pt) {
                int pp = pwarp + pt * 16 + lq;
                red[jg * 128 + pp]     = sp[pt][0];
                red[jg * 128 + pp + 8] = sp[pt][1];
            }
        }
        NB_SYNC(5, 256);                            // consumers only

        if (tid < 128) {
            float t = red[tid] + red[128 + tid] + red[256 + tid] + red[384 + tid];
            out[pbase + tid] = t + b3[0] + sbS[tid];
        }
    } else {
        // ================= PRODUCERS (4 warps): stage W2 + gather =================
        const int ptid = tid - 256;                 // 0..127
        const int kseg = ptid & 7;                  // 16B granule in chunk
        const int pr   = ptid >> 3;                 // 0..15
        const float4* TA4 = (const float4*)d_TA;
        const float4* TB4 = (const float4*)d_TB;
        const float4* TP4 = (const float4*)d_TPHI;
        unsigned w_smem_base = (unsigned)__cvta_generic_to_shared(Wb);

        for (int ch = 0; ch < 5; ++ch) {
            const int buf = ch & 1;
            if (ch >= 2) NB_SYNC(3 + buf, NTHR);    // wait empty[buf]

            // W2 chunk via cp.async (1280 granules / 128 threads = 10 each)
            {
                unsigned wb = w_smem_base + buf * (32 * 168 * 4);
                const int rows = (ch == 4) ? 24 : 32;
                for (int i4 = ptid; i4 < rows * 40; i4 += 128) {
                    int row = i4 / 40;
                    int j4  = i4 - row * 40;
                    cpa16(wb + (row * 168 + j4 * 4) * 4,
                          d_W2t + (ch * 32 + row) * HPAD + j4 * 4, 16);
                }
                cpa_commit();
            }

            // gather: 1024 slots / 128 threads = 8 slots, all LDGs batched
            {
                unsigned* hb = Hb + buf * (128 * 36);
                const int kk = ch * 8 + kseg;       // 0..39 (38,39 rows unread)
                float4 va[8], vb4[8], vc[8];
                #pragma unroll
                for (int u = 0; u < 8; ++u) {
                    int p = pr + u * 16;
                    va[u]  = TA4[mS[p] * 40 + kk];
                    vb4[u] = TB4[aS[p] * 40 + kk];
                    vc[u]  = TP4[cS[p] * 40 + kk];
                }
                #pragma unroll
                for (int u = 0; u < 8; ++u) {
                    int p = pr + u * 16;
                    uint4 o;
                    o.x = __float_as_uint(fmaxf(va[u].x + vb4[u].x + vc[u].x, 0.0f));
                    o.y = __float_as_uint(fmaxf(va[u].y + vb4[u].y + vc[u].y, 0.0f));
                    o.z = __float_as_uint(fmaxf(va[u].z + vb4[u].z + vc[u].z, 0.0f));
                    o.w = __float_as_uint(fmaxf(va[u].w + vb4[u].w + vc[u].w, 0.0f));
                    *(uint4*)(hb + p * 36 + kseg * 4) = o;
                }
            }

            cpa_wait0();                            // W2 cp.asyncs landed
            NB_ARRIVE(1 + buf, NTHR);               // signal full[buf]
        }
    }
}

// =====================================================================
// launch
// =====================================================================
extern "C" void kernel_launch(void* const* d_in, const int* in_sizes, int n_in,
                              void* d_out, int out_size)
{
    const float* g    = (const float*)d_in[0];
    const float* s_m  = (const float*)d_in[1];
    const int*   mids = (const int*)d_in[2];
    const int*   aids = (const int*)d_in[3];
    const int*   dist = (const int*)d_in[4];
    const int*   genr = (const int*)d_in[5];
    const int*   spk  = (const int*)d_in[6];
    const float* de   = (const float*)d_in[7];
    const float* ge   = (const float*)d_in[8];
    const float* se   = (const float*)d_in[9];
    const float* W1   = (const float*)d_in[10];
    const float* b1   = (const float*)d_in[11];
    const float* W2   = (const float*)d_in[12];
    const float* b2   = (const float*)d_in[13];
    const float* W3   = (const float*)d_in[14];
    const float* b3   = (const float*)d_in[15];
    float* out = (float*)d_out;

    static int attr_done = 0;
    if (!attr_done) {
        cudaFuncSetAttribute(k_precompute, cudaFuncAttributeMaxDynamicSharedMemorySize, PRE_SMEM_B);
        cudaFuncSetAttribute(k_pairs, cudaFuncAttributeMaxDynamicSharedMemorySize, KP_SMEM_B);
        attr_done = 1;
    }

    k_prepphi<<<PREP_BLOCKS + NPHI, 256>>>(W2, de, ge, se, W1, b1);
    k_precompute<<<dim3(16, NSLOTS), 256, PRE_SMEM_B>>>(g, W1);
    k_reduce<<<(N_SPANS * HPAD / 2 + 255) / 256, 256>>>();
    k_pairs<<<NPAIRS / 128, NTHR, KP_SMEM_B>>>(s_m, mids, aids, dist, genr, spk,
                                               W3, b2, b3, out);
}

// round 12
// speedup vs baseline: 1.9528x; 1.8512x over previous
#include <cuda_runtime.h>
#include <cuda_fp16.h>

// ---------------- problem constants ----------------
#define N_SPANS   2000
#define D_SPAN    1220
#define NPAIRS    65536
#define HID       150
#define HPAD      160          // padded hidden dim (zero-padded 150..159)
#define NPHI      189          // 9 bins * 7 genres * 3 speakers
#define NSLOTS    18           // 6 TA + 6 TB(lin) + 6 TB(sq) k-slots
#define ROW_H     192          // halves per padded fp16 table row (384 B)
#define KH        160          // padded layer-2 K for fp16 mma (10 k16 steps)

// ---------------- scratch (static device memory; no allocs) ----------------
__device__ __align__(256) float  d_Cpart[NSLOTS][N_SPANS * HPAD];
__device__ __align__(256) __half d_TAh[N_SPANS * ROW_H];
__device__ __align__(256) __half d_TBh[N_SPANS * ROW_H];
__device__ __align__(256) __half d_TPHIh[NPHI * ROW_H];
__device__ __align__(256) __half d_W2th[KH * KH];   // W2 transposed [j][k], fp16

__device__ __forceinline__ unsigned f2tf32(float x) {
    unsigned r;
    asm("cvt.rna.tf32.f32 %0, %1;" : "=r"(r) : "f"(x));
    return r;
}

// tf32 mma for k_precompute (unchanged)
__device__ __forceinline__ void mma_tf32(float& c0, float& c1, float& c2, float& c3,
                                         unsigned a0, unsigned a1, unsigned a2, unsigned a3,
                                         unsigned b0, unsigned b1)
{
    asm volatile(
        "mma.sync.aligned.m16n8k8.row.col.f32.tf32.tf32.f32 "
        "{%0,%1,%2,%3}, {%4,%5,%6,%7}, {%8,%9}, {%0,%1,%2,%3};\n"
        : "+f"(c0), "+f"(c1), "+f"(c2), "+f"(c3)
        : "r"(a0), "r"(a1), "r"(a2), "r"(a3), "r"(b0), "r"(b1));
}

// fp16 mma for k_pairs
__device__ __forceinline__ void mma_f16(float& c0, float& c1, float& c2, float& c3,
                                        unsigned a0, unsigned a1, unsigned a2, unsigned a3,
                                        unsigned b0, unsigned b1)
{
    asm volatile(
        "mma.sync.aligned.m16n8k16.row.col.f32.f16.f16.f32 "
        "{%0,%1,%2,%3}, {%4,%5,%6,%7}, {%8,%9}, {%0,%1,%2,%3};\n"
        : "+f"(c0), "+f"(c1), "+f"(c2), "+f"(c3)
        : "r"(a0), "r"(a1), "r"(a2), "r"(a3), "r"(b0), "r"(b1));
}

__device__ __forceinline__ unsigned h2addrelu(unsigned a, unsigned b, unsigned c) {
    __half2 s = __hadd2(__hadd2(*(__half2*)&a, *(__half2*)&b), *(__half2*)&c);
    s = __hmax2(s, __half2half2(__ushort_as_half(0)));
    return *(unsigned*)&s;
}

__device__ __forceinline__ void cpa16(unsigned dst, const void* src, int srcsize) {
    asm volatile("cp.async.ca.shared.global [%0], [%1], 16, %2;\n"
                 :: "r"(dst), "l"(src), "r"(srcsize));
}
__device__ __forceinline__ void cpa8(unsigned dst, const void* src, int srcsize) {
    asm volatile("cp.async.ca.shared.global [%0], [%1], 8, %2;\n"
                 :: "r"(dst), "l"(src), "r"(srcsize));
}
__device__ __forceinline__ void cpa_commit() {
    asm volatile("cp.async.commit_group;\n");
}
__device__ __forceinline__ void cpa_wait0() {
    asm volatile("cp.async.wait_group 0;\n");
}

// =====================================================================
// K_prepphi: blocks 0..99  -> W2 transposed fp16 [j=160][k=160]
//            blocks 100..288 -> TPHI rows (fp16, padded to 192 halves)
// =====================================================================
#define PREP_BLOCKS 100        // 100*256 = 25600 = KH*KH exactly

__global__ void k_prepphi(const float* __restrict__ W2,
                          const float* __restrict__ de, const float* __restrict__ ge,
                          const float* __restrict__ se, const float* __restrict__ W1,
                          const float* __restrict__ b1)
{
    if (blockIdx.x < PREP_BLOCKS) {
        int idx = blockIdx.x * 256 + threadIdx.x;     // < KH*KH
        int j = idx / KH;
        int k = idx % KH;
        float v = (j < HID && k < HID) ? W2[k * HID + j] : 0.0f;
        d_W2th[j * KH + k] = __float2half_rn(v);
    } else {
        int c = blockIdx.x - PREP_BLOCKS;             // 0..NPHI-1
        int j = threadIdx.x;
        if (j < KH) {
            int bin = c / 21;
            int r   = c % 21;
            int gg  = r / 3;
            int ss  = r % 3;
            float v = 0.0f;
            if (j < HID) {
                v = b1[j];
                #pragma unroll
                for (int t = 0; t < 20; ++t) {
                    v += de[bin * 20 + t] * W1[(3660 + t) * HID + j];
                    v += ge[gg  * 20 + t] * W1[(3680 + t) * HID + j];
                    v += se[ss  * 20 + t] * W1[(3700 + t) * HID + j];
                }
            }
            d_TPHIh[c * ROW_H + j] = __float2half_rn(v);
        }
    }
}

// =====================================================================
// K1: precompute TA / TB partials with TF32 mma, cp.async staging,
//     single-sync double-buffered chunk pipeline.  (unchanged, fp32 out)
// =====================================================================
#define PRE_ATF_W   (2 * 128 * 36)     // 9216 words
#define PRE_BTF_W   (2 * 32 * 168)     // 10752 words
#define PRE_SMEM_W  (PRE_ATF_W + PRE_BTF_W)
#define PRE_SMEM_B  (PRE_SMEM_W * 4)

__global__ __launch_bounds__(256, 2) void k_precompute(const float* __restrict__ g,
                                                       const float* __restrict__ W1)
{
    extern __shared__ unsigned SP[];
    unsigned* Atf = SP;                 // 2 buffers of [128][36]
    unsigned* Btf = SP + PRE_ATF_W;     // 2 buffers of [32][168]

    const int mtile = blockIdx.x;          // 0..15
    const int slot  = blockIdx.y;          // 0..17
    const int mbase = mtile * 128;
    const int type  = slot / 6;            // 0 TA, 1 TBlin, 2 TBsq
    const int sub   = slot % 6;
    const int kbase = sub * 204;
    const int klen  = (sub == 5) ? 200 : 204;
    const int wrow0 = type * 1220;
    const bool sq   = (type == 2);

    const int tid  = threadIdx.x;
    const int lane = tid & 31;
    const int wid  = tid >> 5;
    const int mwarp = (wid & 1) * 64;
    const int jwarp = (wid >> 1) * 40;
    const int lq = lane >> 2;
    const int lr = lane & 3;

    const int am = tid >> 3;
    const int aq = tid & 7;
    const int brow = tid >> 3;
    const int bj   = tid & 7;

    unsigned a_smem_base = (unsigned)__cvta_generic_to_shared(Atf);
    unsigned b_smem_base = (unsigned)__cvta_generic_to_shared(Btf);

    float c[4][5][4];
    #pragma unroll
    for (int pt = 0; pt < 4; ++pt)
        #pragma unroll
        for (int nt = 0; nt < 5; ++nt)
            #pragma unroll
            for (int i = 0; i < 4; ++i) c[pt][nt][i] = 0.0f;

    auto stageA = [&](int ch, int bsel) {
        unsigned abase = a_smem_base + bsel * (128 * 36 * 4);
        if (!sq) {
            #pragma unroll
            for (int it = 0; it < 4; ++it) {
                int m  = am + it * 32;
                int kk = ch * 32 + aq * 4;
                int ok = ((mbase + m) < N_SPANS && kk < klen) ? 16 : 0;
                const float* src = g + (size_t)(mbase + (ok ? m : 0)) * D_SPAN
                                     + (ok ? (kbase + kk) : 0);
                cpa16(abase + (m * 36 + aq * 4) * 4, src, ok);
            }
        } else {
            unsigned* ab = (unsigned*)Atf + bsel * (128 * 36);
            #pragma unroll
            for (int it = 0; it < 4; ++it) {
                int m  = am + it * 32;
                int kk = ch * 32 + aq * 4;
                float4 v = make_float4(0.f, 0.f, 0.f, 0.f);
                if ((mbase + m) < N_SPANS && kk < klen)
                    v = *(const float4*)(g + (size_t)(mbase + m) * D_SPAN + kbase + kk);
                uint4 o;
                o.x = f2tf32(v.x * v.x);
                o.y = f2tf32(v.y * v.y);
                o.z = f2tf32(v.z * v.z);
                o.w = f2tf32(v.w * v.w);
                *(uint4*)(ab + m * 36 + aq * 4) = o;
            }
        }
    };
    auto stageB = [&](int ch, int bsel) {
        unsigned bbase = b_smem_base + bsel * (32 * 168 * 4);
        int kk = ch * 32 + brow;
        const float* rowp = W1 + (size_t)(wrow0 + kbase + ((kk < klen) ? kk : 0)) * HID;
        #pragma unroll
        for (int s = 0; s < 10; ++s) {
            int j2 = bj + 8 * s;
            int ok = (kk < klen && j2 < 75) ? 8 : 0;
            cpa8(bbase + (brow * 168 + j2 * 2) * 4, rowp + (ok ? j2 * 2 : 0), ok);
        }
    };

    stageA(0, 0);
    stageB(0, 0);
    cpa_commit();

    for (int ch = 0; ch < 7; ++ch) {
        const int buf = ch & 1;
        cpa_wait0();
        __syncthreads();
        if (ch < 6) {
            stageA(ch + 1, buf ^ 1);
            stageB(ch + 1, buf ^ 1);
            cpa_commit();
        }
        const unsigned* Ab = (const unsigned*)Atf + buf * (128 * 36);
        const unsigned* Bb = (const unsigned*)Btf + buf * (32 * 168);
        #pragma unroll
        for (int ks = 0; ks < 4; ++ks) {
            const int kcs = ks * 8;
            unsigned bfr[5][2];
            #pragma unroll
            for (int nt = 0; nt < 5; ++nt) {
                int j = jwarp + nt * 8 + lq;
                bfr[nt][0] = Bb[(kcs + lr)     * 168 + j];
                bfr[nt][1] = Bb[(kcs + lr + 4) * 168 + j];
            }
            #pragma unroll
            for (int pt = 0; pt < 4; ++pt) {
                int m = mwarp + pt * 16 + lq;
                unsigned a0 = Ab[m       * 36 + kcs + lr];
                unsigned a1 = Ab[(m + 8) * 36 + kcs + lr];
                unsigned a2 = Ab[m       * 36 + kcs + lr + 4];
                unsigned a3 = Ab[(m + 8) * 36 + kcs + lr + 4];
                #pragma unroll
                for (int nt = 0; nt < 5; ++nt)
                    mma_tf32(c[pt][nt][0], c[pt][nt][1], c[pt][nt][2], c[pt][nt][3],
                             a0, a1, a2, a3, bfr[nt][0], bfr[nt][1]);
            }
        }
    }

    float* dst = d_Cpart[slot];
    #pragma unroll
    for (int pt = 0; pt < 4; ++pt) {
        int m0 = mbase + mwarp + pt * 16 + lq;
        #pragma unroll
        for (int nt = 0; nt < 5; ++nt) {
            int j = jwarp + nt * 8 + 2 * lr;
            if (m0 < N_SPANS)
                *(float2*)(dst + (size_t)m0 * HPAD + j) = make_float2(c[pt][nt][0], c[pt][nt][1]);
            if (m0 + 8 < N_SPANS)
                *(float2*)(dst + (size_t)(m0 + 8) * HPAD + j) = make_float2(c[pt][nt][2], c[pt][nt][3]);
        }
    }
}

// =====================================================================
// K2: reduce k-split partials into fp16 TA / TB tables (padded rows)
// =====================================================================
__global__ void k_reduce()
{
    int idx2 = blockIdx.x * blockDim.x + threadIdx.x;
    if (idx2 < N_SPANS * HPAD / 2) {
        float2 ta = make_float2(0.f, 0.f);
        float2 tb = ta;
        #pragma unroll
        for (int s = 0; s < 6; ++s) {
            float2 v = ((const float2*)d_Cpart[s])[idx2];
            ta.x += v.x; ta.y += v.y;
        }
        #pragma unroll
        for (int s = 6; s < 18; ++s) {
            float2 v = ((const float2*)d_Cpart[s])[idx2];
            tb.x += v.x; tb.y += v.y;
        }
        int m = idx2 / 80;
        int q = idx2 % 80;
        *(__half2*)(d_TAh + (size_t)m * ROW_H + 2 * q) = __floats2half2_rn(ta.x, ta.y);
        *(__half2*)(d_TBh + (size_t)m * ROW_H + 2 * q) = __floats2half2_rn(tb.x, tb.y);
    }
}

// =====================================================================
// K3: fused pair kernel — FP16 gather + m16n8k16 fp16 MMA.
//   512 blocks x 256 threads; 128 pairs / block; double-buffered chunks.
//   H1 smem [p][k-chunk] fp16, row stride 20 words (conflict-free).
//   W2T smem [j][k-chunk] fp16, row stride 20 words, via cp.async.
// =====================================================================
#define H_STR     20                     // words per row (16 data + 4 pad)
#define KP_HB_W   (2 * 128 * H_STR)      // 5120 words
#define KP_WB_W   (2 * 160 * H_STR)      // 6400 words
#define KP_OFF_W3 (KP_HB_W + KP_WB_W)    // 11520
#define KP_OFF_B2 (KP_OFF_W3 + HPAD)
#define KP_OFF_SB (KP_OFF_B2 + HPAD)
#define KP_OFF_M  (KP_OFF_SB + 128)
#define KP_OFF_A  (KP_OFF_M + 128)
#define KP_OFF_C  (KP_OFF_A + 128)
#define KP_SMEM_W (KP_OFF_C + 128)
#define KP_SMEM_B (KP_SMEM_W * 4)

__global__ __launch_bounds__(256, 2) void k_pairs(
    const float* __restrict__ s_m, const int* __restrict__ mids,
    const int* __restrict__ aids, const int* __restrict__ dist,
    const int* __restrict__ genre, const int* __restrict__ spk,
    const float* __restrict__ W3, const float* __restrict__ b2,
    const float* __restrict__ b3, float* __restrict__ out)
{
    extern __shared__ unsigned SU[];
    unsigned* Hb  = SU;                       // 2 x [128][20]
    unsigned* Wb  = SU + KP_HB_W;             // 2 x [160][20]
    float*    W3s = (float*)(SU + KP_OFF_W3);
    float*    b2s = (float*)(SU + KP_OFF_B2);
    float*    sbS = (float*)(SU + KP_OFF_SB);
    int*      mS  = (int*)(SU + KP_OFF_M);
    int*      aS  = (int*)(SU + KP_OFF_A);
    int*      cS  = (int*)(SU + KP_OFF_C);
    float*    red = (float*)(Wb + 160 * H_STR);  // alias Wb buffer 1 (last chunk uses buf 0)

    const int tid   = threadIdx.x;
    const int lane  = tid & 31;
    const int wid   = tid >> 5;
    const int pbase = blockIdx.x * 128;

    // ---- per-pair metadata -> smem ----
    if (tid < 128) {
        int p = pbase + tid;
        int m = mids[p];
        int a = aids[p];
        mS[tid] = m;
        aS[tid] = a;
        int d = dist[p];
        int bin;
        if      (d >= 64) bin = 8;
        else if (d >= 32) bin = 7;
        else if (d >= 16) bin = 6;
        else if (d >= 8)  bin = 5;
        else if (d >= 5)  bin = 4;
        else              bin = (d >= 1) ? (d - 1) : 0;
        cS[tid] = (bin * 7 + genre[p]) * 3 + spk[p];
        sbS[tid] = s_m[m] + s_m[a];
    }
    if (tid < HPAD) {
        float w3v = 0.0f, b2v = 0.0f;
        if (tid < HID) { w3v = W3[tid]; b2v = b2[tid]; }
        W3s[tid] = w3v;
        b2s[tid] = b2v;
    }

    unsigned w_smem_base = (unsigned)__cvta_generic_to_shared(Wb);

    // W2T staging: 160 rows x 4 granules of 16B per chunk
    auto stageW2 = [&](int ch, int bsel) {
        unsigned wb = w_smem_base + bsel * (160 * H_STR * 4);
        for (int i4 = tid; i4 < 160 * 4; i4 += 256) {
            int row = i4 >> 2;
            int seg = i4 & 3;
            cpa16(wb + (row * H_STR + seg * 4) * 4,
                  (const char*)d_W2th + row * (KH * 2) + ch * 64 + seg * 16, 16);
        }
    };

    // coalesced fp16 gather: 4 lanes cooperate on one pair's 64B chunk row
    const int kseg = tid & 3;
    const int prb  = tid >> 2;              // 0..63
    auto gather = [&](int ch, int bsel) {
        unsigned* hb = Hb + bsel * (128 * H_STR);
        const int g = ch * 4 + kseg;        // granule 0..19 (16B each)
        #pragma unroll
        for (int it = 0; it < 2; ++it) {
            int p = prb + it * 64;
            const char* ta = (const char*)d_TAh   + (size_t)mS[p] * (ROW_H * 2) + g * 16;
            const char* tb = (const char*)d_TBh   + (size_t)aS[p] * (ROW_H * 2) + g * 16;
            const char* tc = (const char*)d_TPHIh + (size_t)cS[p] * (ROW_H * 2) + g * 16;
            uint4 va = *(const uint4*)ta;
            uint4 vb = *(const uint4*)tb;
            uint4 vc = *(const uint4*)tc;
            uint4 o;
            o.x = h2addrelu(va.x, vb.x, vc.x);
            o.y = h2addrelu(va.y, vb.y, vc.y);
            o.z = h2addrelu(va.z, vb.z, vc.z);
            o.w = h2addrelu(va.w, vb.w, vc.w);
            *(uint4*)(hb + p * H_STR + kseg * 4) = o;
        }
    };

    // ---- MMA tiling ----
    const int pwarp = (wid & 1) * 64;
    const int jg    = wid >> 1;
    const int jwarp = jg * 40;
    const int lq = lane >> 2;
    const int lr = lane & 3;

    float c[4][5][4];
    #pragma unroll
    for (int pt = 0; pt < 4; ++pt)
        #pragma unroll
        for (int nt = 0; nt < 5; ++nt)
            #pragma unroll
            for (int i = 0; i < 4; ++i) c[pt][nt][i] = 0.0f;

    // ---- pipeline ----
    stageW2(0, 0);
    cpa_commit();
    __syncthreads();                    // metadata visible
    gather(0, 0);

    for (int ch = 0; ch < 5; ++ch) {
        const int buf = ch & 1;
        cpa_wait0();
        __syncthreads();                // H1[buf] + W2[buf] ready
        if (ch < 4) {
            stageW2(ch + 1, buf ^ 1);
            cpa_commit();
            gather(ch + 1, buf ^ 1);
        }
        const unsigned* hb = Hb + buf * (128 * H_STR);
        const unsigned* wb = Wb + buf * (160 * H_STR);
        #pragma unroll
        for (int ks = 0; ks < 2; ++ks) {          // 2 k16-steps per 32-k chunk
            const int kw = ks * 8;                // word offset within row
            unsigned bfr[5][2];
            #pragma unroll
            for (int nt = 0; nt < 5; ++nt) {
                int j = jwarp + nt * 8 + lq;
                bfr[nt][0] = wb[j * H_STR + kw + lr];
                bfr[nt][1] = wb[j * H_STR + kw + lr + 4];
            }
            #pragma unroll
            for (int pt = 0; pt < 4; ++pt) {
                int pp = pwarp + pt * 16 + lq;
                unsigned a0 = hb[pp       * H_STR + kw + lr];
                unsigned a1 = hb[(pp + 8) * H_STR + kw + lr];
                unsigned a2 = hb[pp       * H_STR + kw + lr + 4];
                unsigned a3 = hb[(pp + 8) * H_STR + kw + lr + 4];
                #pragma unroll
                for (int nt = 0; nt < 5; ++nt)
                    mma_f16(c[pt][nt][0], c[pt][nt][1], c[pt][nt][2], c[pt][nt][3],
                            a0, a1, a2, a3, bfr[nt][0], bfr[nt][1]);
            }
        }
    }

    // ---- epilogue: relu(+b2) dot W3 ----
    float sp[4][2];
    #pragma unroll
    for (int pt = 0; pt < 4; ++pt) { sp[pt][0] = 0.0f; sp[pt][1] = 0.0f; }

    #pragma unroll
    for (int nt = 0; nt < 5; ++nt) {
        int j = jwarp + nt * 8 + 2 * lr;
        float w3a = W3s[j],     b2a = b2s[j];
        float w3b = W3s[j + 1], b2b = b2s[j + 1];
        #pragma unroll
        for (int pt = 0; pt < 4; ++pt) {
            sp[pt][0] += fmaxf(c[pt][nt][0] + b2a, 0.0f) * w3a;
            sp[pt][0] += fmaxf(c[pt][nt][1] + b2b, 0.0f) * w3b;
            sp[pt][1] += fmaxf(c[pt][nt][2] + b2a, 0.0f) * w3a;
            sp[pt][1] += fmaxf(c[pt][nt][3] + b2b, 0.0f) * w3b;
        }
    }
    #pragma unroll
    for (int pt = 0; pt < 4; ++pt) {
        #pragma unroll
        for (int h = 0; h < 2; ++h) {
            sp[pt][h] += __shfl_xor_sync(0xffffffffu, sp[pt][h], 1);
            sp[pt][h] += __shfl_xor_sync(0xffffffffu, sp[pt][h], 2);
        }
    }

    __syncthreads();   // all buf-1 reads done (last MMA chunk used buf 0)
    if (lr == 0) {
        #pragma unroll
        for (int pt = 0; pt < 4; ++pt) {
            int pp = pwarp + pt * 16 + lq;
            red[jg * 128 + pp]     = sp[pt][0];
            red[jg * 128 + pp + 8] = sp[pt][1];
        }
    }
    __syncthreads();

    if (tid < 128) {
        float t = red[tid] + red[128 + tid] + red[256 + tid] + red[384 + tid];
        out[pbase + tid] = t + b3[0] + sbS[tid];
    }
}

// =====================================================================
// launch
// =====================================================================
extern "C" void kernel_launch(void* const* d_in, const int* in_sizes, int n_in,
                              void* d_out, int out_size)
{
    const float* g    = (const float*)d_in[0];
    const float* s_m  = (const float*)d_in[1];
    const int*   mids = (const int*)d_in[2];
    const int*   aids = (const int*)d_in[3];
    const int*   dist = (const int*)d_in[4];
    const int*   genr = (const int*)d_in[5];
    const int*   spk  = (const int*)d_in[6];
    const float* de   = (const float*)d_in[7];
    const float* ge   = (const float*)d_in[8];
    const float* se   = (const float*)d_in[9];
    const float* W1   = (const float*)d_in[10];
    const float* b1   = (const float*)d_in[11];
    const float* W2   = (const float*)d_in[12];
    const float* b2   = (const float*)d_in[13];
    const float* W3   = (const float*)d_in[14];
    const float* b3   = (const float*)d_in[15];
    float* out = (float*)d_out;

    static int attr_done = 0;
    if (!attr_done) {
        cudaFuncSetAttribute(k_precompute, cudaFuncAttributeMaxDynamicSharedMemorySize, PRE_SMEM_B);
        cudaFuncSetAttribute(k_pairs, cudaFuncAttributeMaxDynamicSharedMemorySize, KP_SMEM_B);
        attr_done = 1;
    }

    k_prepphi<<<PREP_BLOCKS + NPHI, 256>>>(W2, de, ge, se, W1, b1);
    k_precompute<<<dim3(16, NSLOTS), 256, PRE_SMEM_B>>>(g, W1);
    k_reduce<<<(N_SPANS * HPAD / 2 + 255) / 256, 256>>>();
    k_pairs<<<NPAIRS / 128, 256, KP_SMEM_B>>>(s_m, mids, aids, dist, genr, spk,
                                              W3, b2, b3, out);
}

// round 14
// speedup vs baseline: 2.1765x; 1.1146x over previous
#include <cuda_runtime.h>
#include <cuda_fp16.h>

// ---------------- problem constants ----------------
#define N_SPANS   2000
#define D_SPAN    1220
#define NPAIRS    65536
#define HID       150
#define HPAD      160          // padded hidden dim (zero-padded 150..159)
#define NPHI      189          // 9 bins * 7 genres * 3 speakers
#define NSLOTS    18           // 6 k-slots per type x 3 types
#define ROW_H     192          // halves per padded fp16 table row (384 B)
#define KH        160          // padded layer-2 K for fp16 mma
#define W1T_KS    1232         // padded k-extent of W1^T rows (halves)

// ---------------- scratch (static device memory; no allocs) ----------------
__device__ __align__(256) float  d_Cpart[NSLOTS][N_SPANS * HPAD];
__device__ __align__(256) __half d_TAh[N_SPANS * ROW_H];
__device__ __align__(256) __half d_TBh[N_SPANS * ROW_H];
__device__ __align__(256) __half d_TPHIh[NPHI * ROW_H];
__device__ __align__(256) __half d_W2th[KH * KH];          // W2^T [j][k] fp16
__device__ __align__(256) __half d_W1Th[3 * 160 * W1T_KS]; // W1^T [type][j][k] fp16

__device__ __forceinline__ unsigned packh2(float x, float y) {
    __half2 h = __floats2half2_rn(x, y);
    return *(unsigned*)&h;
}

// fp16 mma (m16n8k16, row.col, f32 accum)
__device__ __forceinline__ void mma_f16(float& c0, float& c1, float& c2, float& c3,
                                        unsigned a0, unsigned a1, unsigned a2, unsigned a3,
                                        unsigned b0, unsigned b1)
{
    asm volatile(
        "mma.sync.aligned.m16n8k16.row.col.f32.f16.f16.f32 "
        "{%0,%1,%2,%3}, {%4,%5,%6,%7}, {%8,%9}, {%0,%1,%2,%3};\n"
        : "+f"(c0), "+f"(c1), "+f"(c2), "+f"(c3)
        : "r"(a0), "r"(a1), "r"(a2), "r"(a3), "r"(b0), "r"(b1));
}

__device__ __forceinline__ unsigned h2addrelu(unsigned a, unsigned b, unsigned c) {
    __half2 s = __hadd2(__hadd2(*(__half2*)&a, *(__half2*)&b), *(__half2*)&c);
    s = __hmax2(s, __half2half2(__ushort_as_half(0)));
    return *(unsigned*)&s;
}

__device__ __forceinline__ void cpa16(unsigned dst, const void* src, int srcsize) {
    asm volatile("cp.async.ca.shared.global [%0], [%1], 16, %2;\n"
                 :: "r"(dst), "l"(src), "r"(srcsize));
}
__device__ __forceinline__ void cpa_commit() {
    asm volatile("cp.async.commit_group;\n");
}
__device__ __forceinline__ void cpa_wait0() {
    asm volatile("cp.async.wait_group 0;\n");
}

// =====================================================================
// K_prepphi: blocks [0,100)   -> W2^T fp16 [j=160][k=160]
//            blocks [100,289) -> TPHI rows (fp16, stride 192)
//            blocks [289,406) -> W1^T fp16 [type][j][1232] (smem transpose)
// =====================================================================
#define PREP_BLOCKS 100        // 100*256 = 25600 = KH*KH exactly
#define PHI_END     (PREP_BLOCKS + NPHI)

__global__ void k_prepphi(const float* __restrict__ W2,
                          const float* __restrict__ de, const float* __restrict__ ge,
                          const float* __restrict__ se, const float* __restrict__ W1,
                          const float* __restrict__ b1)
{
    if (blockIdx.x < PREP_BLOCKS) {
        int idx = blockIdx.x * 256 + threadIdx.x;     // < KH*KH
        int j = idx / KH;
        int k = idx % KH;
        float v = (j < HID && k < HID) ? W2[k * HID + j] : 0.0f;
        d_W2th[j * KH + k] = __float2half_rn(v);
    } else if (blockIdx.x < PHI_END) {
        int c = blockIdx.x - PREP_BLOCKS;             // 0..NPHI-1
        int j = threadIdx.x;
        if (j < KH) {
            int bin = c / 21;
            int r   = c % 21;
            int gg  = r / 3;
            int ss  = r % 3;
            float v = 0.0f;
            if (j < HID) {
                v = b1[j];
                #pragma unroll
                for (int t = 0; t < 20; ++t) {
                    v += de[bin * 20 + t] * W1[(3660 + t) * HID + j];
                    v += ge[gg  * 20 + t] * W1[(3680 + t) * HID + j];
                    v += se[ss  * 20 + t] * W1[(3700 + t) * HID + j];
                }
            }
            d_TPHIh[c * ROW_H + j] = __float2half_rn(v);
        }
    } else {
        // W1^T transpose: block -> (type, ktile of 32)
        int b     = blockIdx.x - PHI_END;             // 0..116
        int type  = b / 39;
        int ktile = b % 39;
        int kb2   = ktile * 32;
        __shared__ __half sT[160 * 33];
        for (int i = threadIdx.x; i < 160 * 33; i += 256)
            sT[i] = __ushort_as_half(0);
        __syncthreads();
        int wrow0 = type * 1220 + kb2;
        for (int i = threadIdx.x; i < 32 * HID; i += 256) {
            int kk = i / HID;
            int j  = i % HID;
            if (kb2 + kk < 1220)
                sT[j * 33 + kk] = __float2half_rn(W1[(wrow0 + kk) * HID + j]);
        }
        __syncthreads();
        __half* dstb = d_W1Th + (size_t)type * 160 * W1T_KS;
        for (int i = threadIdx.x; i < 160 * 32; i += 256) {
            int j  = i >> 5;
            int kk = i & 31;
            if (kb2 + kk < W1T_KS)
                dstb[(size_t)j * W1T_KS + kb2 + kk] = sT[j * 33 + kk];
        }
    }
}

// =====================================================================
// K1: precompute TA / TB partials with FP16 mma (m16n8k16).
//   grid = (16 mtiles, 18 slots), 256 threads, BM=128, BN=160.
//   type = slot/6 (0 TA, 1 TBlin, 2 TBsq=g^2); sub = slot%6.
//   K splits per type: {192,192,192,192,224,232(ragged; W1^T zero-padded)}.
//   Chunks of 64 halves; A staged via LDG+cvt+STS [m][k] stride 36 words;
//   B via raw cp.async from W1^T [j][k] stride 36 words.
// =====================================================================
#define PRE_ATF_W   (2 * 128 * 36)     // 9216 words
#define PRE_BTF_W   (2 * 160 * 36)     // 11520 words
#define PRE_SMEM_W  (PRE_ATF_W + PRE_BTF_W)
#define PRE_SMEM_B  (PRE_SMEM_W * 4)

__global__ __launch_bounds__(256, 2) void k_precompute(const float* __restrict__ g)
{
    extern __shared__ unsigned SP[];
    unsigned* Atf = SP;                 // 2 buffers of [128][36] words (fp16 pairs)
    unsigned* Btf = SP + PRE_ATF_W;     // 2 buffers of [160][36] words

    const int mtile = blockIdx.x;          // 0..15
    const int slot  = blockIdx.y;          // 0..17
    const int mbase = mtile * 128;
    const int type  = slot / 6;
    const int sub   = slot % 6;
    const int kbase = (sub < 4) ? sub * 192 : ((sub == 4) ? 768 : 992);
    const int klen  = (sub < 4) ? 192 : ((sub == 4) ? 224 : 232);
    const int nch   = (klen + 63) >> 6;    // 3 or 4
    const bool sq   = (type == 2);
    const __half* W1Tb = d_W1Th + (size_t)type * 160 * W1T_KS;

    const int tid  = threadIdx.x;
    const int lane = tid & 31;
    const int wid  = tid >> 5;
    const int mwarp = (wid & 1) * 64;
    const int jwarp = (wid >> 1) * 40;
    const int lq = lane >> 2;
    const int lr = lane & 3;

    const int am = tid >> 3;            // A: m row base (m = am + 32*it)
    const int aq = tid & 7;             // A: 8-half octet within 64-half chunk

    unsigned b_smem_base = (unsigned)__cvta_generic_to_shared(Btf);

    float c[4][5][4];
    #pragma unroll
    for (int pt = 0; pt < 4; ++pt)
        #pragma unroll
        for (int nt = 0; nt < 5; ++nt)
            #pragma unroll
            for (int i = 0; i < 4; ++i) c[pt][nt][i] = 0.0f;

    auto stageA = [&](int ch, int bsel) {
        unsigned* ab = Atf + bsel * (128 * 36);
        const int kk0 = ch * 64 + aq * 8;     // local half index (mult of 8)
        const int kg0 = kbase + kk0;          // global k'
        #pragma unroll
        for (int it = 0; it < 4; ++it) {
            int m = am + it * 32;
            bool mok = (mbase + m) < N_SPANS && (kk0 < klen);
            float4 v1 = make_float4(0.f, 0.f, 0.f, 0.f);
            float4 v2 = v1;
            const float* src = g + (size_t)(mbase + m) * D_SPAN + kg0;
            if (mok && kg0 < 1220)     v1 = *(const float4*)src;
            if (mok && kg0 + 4 < 1220) v2 = *(const float4*)(src + 4);
            if (sq) {
                v1.x *= v1.x; v1.y *= v1.y; v1.z *= v1.z; v1.w *= v1.w;
                v2.x *= v2.x; v2.y *= v2.y; v2.z *= v2.z; v2.w *= v2.w;
            }
            uint4 o;
            o.x = packh2(v1.x, v1.y);
            o.y = packh2(v1.z, v1.w);
            o.z = packh2(v2.x, v2.y);
            o.w = packh2(v2.z, v2.w);
            *(uint4*)(ab + m * 36 + aq * 4) = o;
        }
    };
    auto stageB = [&](int ch, int bsel) {
        unsigned bb = b_smem_base + bsel * (160 * 36 * 4);
        #pragma unroll
        for (int it = 0; it < 5; ++it) {
            int i  = it * 256 + tid;          // < 1280
            int j  = i >> 3;
            int gq = i & 7;
            int kk = ch * 64 + gq * 8;
            int ok = (kk < klen) ? 16 : 0;
            cpa16(bb + (j * 36 + gq * 4) * 4,
                  W1Tb + (size_t)j * W1T_KS + kbase + (ok ? kk : 0), ok);
        }
    };

    stageA(0, 0);
    stageB(0, 0);
    cpa_commit();

    for (int ch = 0; ch < nch; ++ch) {
        const int buf = ch & 1;
        cpa_wait0();
        __syncthreads();
        if (ch + 1 < nch) {
            stageA(ch + 1, buf ^ 1);
            stageB(ch + 1, buf ^ 1);
            cpa_commit();
        }
        const unsigned* Ab = (const unsigned*)Atf + buf * (128 * 36);
        const unsigned* Bb = (const unsigned*)Btf + buf * (160 * 36);
        #pragma unroll
        for (int ks = 0; ks < 4; ++ks) {          // 4 k16-steps per 64-half chunk
            const int kw = ks * 8;                // word offset within row
            unsigned bfr[5][2];
            #pragma unroll
            for (int nt = 0; nt < 5; ++nt) {
                int j = jwarp + nt * 8 + lq;
                bfr[nt][0] = Bb[j * 36 + kw + lr];
                bfr[nt][1] = Bb[j * 36 + kw + lr + 4];
            }
            #pragma unroll
            for (int pt = 0; pt < 4; ++pt) {
                int m = mwarp + pt * 16 + lq;
                unsigned a0 = Ab[m       * 36 + kw + lr];
                unsigned a1 = Ab[(m + 8) * 36 + kw + lr];
                unsigned a2 = Ab[m       * 36 + kw + lr + 4];
                unsigned a3 = Ab[(m + 8) * 36 + kw + lr + 4];
                #pragma unroll
                for (int nt = 0; nt < 5; ++nt)
                    mma_f16(c[pt][nt][0], c[pt][nt][1], c[pt][nt][2], c[pt][nt][3],
                            a0, a1, a2, a3, bfr[nt][0], bfr[nt][1]);
            }
        }
    }

    float* dst = d_Cpart[slot];
    #pragma unroll
    for (int pt = 0; pt < 4; ++pt) {
        int m0 = mbase + mwarp + pt * 16 + lq;
        #pragma unroll
        for (int nt = 0; nt < 5; ++nt) {
            int j = jwarp + nt * 8 + 2 * lr;
            if (m0 < N_SPANS)
                *(float2*)(dst + (size_t)m0 * HPAD + j) = make_float2(c[pt][nt][0], c[pt][nt][1]);
            if (m0 + 8 < N_SPANS)
                *(float2*)(dst + (size_t)(m0 + 8) * HPAD + j) = make_float2(c[pt][nt][2], c[pt][nt][3]);
        }
    }
}

// =====================================================================
// K2: reduce k-split partials into fp16 TA / TB tables (padded rows)
// =====================================================================
__global__ void k_reduce()
{
    int idx2 = blockIdx.x * blockDim.x + threadIdx.x;
    if (idx2 < N_SPANS * HPAD / 2) {
        float2 ta = make_float2(0.f, 0.f);
        float2 tb = ta;
        #pragma unroll
        for (int s = 0; s < 6; ++s) {
            float2 v = ((const float2*)d_Cpart[s])[idx2];
            ta.x += v.x; ta.y += v.y;
        }
        #pragma unroll
        for (int s = 6; s < 18; ++s) {
            float2 v = ((const float2*)d_Cpart[s])[idx2];
            tb.x += v.x; tb.y += v.y;
        }
        int m = idx2 / 80;
        int q = idx2 % 80;
        *(__half2*)(d_TAh + (size_t)m * ROW_H + 2 * q) = __floats2half2_rn(ta.x, ta.y);
        *(__half2*)(d_TBh + (size_t)m * ROW_H + 2 * q) = __floats2half2_rn(tb.x, tb.y);
    }
}

// =====================================================================
// K3: fused pair kernel — FP16 gather + m16n8k16 fp16 MMA (unchanged R12)
// =====================================================================
#define H_STR     20                     // words per row (16 data + 4 pad)
#define KP_HB_W   (2 * 128 * H_STR)      // 5120 words
#define KP_WB_W   (2 * 160 * H_STR)      // 6400 words
#define KP_OFF_W3 (KP_HB_W + KP_WB_W)    // 11520
#define KP_OFF_B2 (KP_OFF_W3 + HPAD)
#define KP_OFF_SB (KP_OFF_B2 + HPAD)
#define KP_OFF_M  (KP_OFF_SB + 128)
#define KP_OFF_A  (KP_OFF_M + 128)
#define KP_OFF_C  (KP_OFF_A + 128)
#define KP_SMEM_W (KP_OFF_C + 128)
#define KP_SMEM_B (KP_SMEM_W * 4)

__global__ __launch_bounds__(256, 2) void k_pairs(
    const float* __restrict__ s_m, const int* __restrict__ mids,
    const int* __restrict__ aids, const int* __restrict__ dist,
    const int* __restrict__ genre, const int* __restrict__ spk,
    const float* __restrict__ W3, const float* __restrict__ b2,
    const float* __restrict__ b3, float* __restrict__ out)
{
    extern __shared__ unsigned SU[];
    unsigned* Hb  = SU;                       // 2 x [128][20]
    unsigned* Wb  = SU + KP_HB_W;             // 2 x [160][20]
    float*    W3s = (float*)(SU + KP_OFF_W3);
    float*    b2s = (float*)(SU + KP_OFF_B2);
    float*    sbS = (float*)(SU + KP_OFF_SB);
    int*      mS  = (int*)(SU + KP_OFF_M);
    int*      aS  = (int*)(SU + KP_OFF_A);
    int*      cS  = (int*)(SU + KP_OFF_C);
    float*    red = (float*)(Wb + 160 * H_STR);  // alias Wb buffer 1

    const int tid   = threadIdx.x;
    const int lane  = tid & 31;
    const int wid   = tid >> 5;
    const int pbase = blockIdx.x * 128;

    // ---- per-pair metadata -> smem ----
    if (tid < 128) {
        int p = pbase + tid;
        int m = mids[p];
        int a = aids[p];
        mS[tid] = m;
        aS[tid] = a;
        int d = dist[p];
        int bin;
        if      (d >= 64) bin = 8;
        else if (d >= 32) bin = 7;
        else if (d >= 16) bin = 6;
        else if (d >= 8)  bin = 5;
        else if (d >= 5)  bin = 4;
        else              bin = (d >= 1) ? (d - 1) : 0;
        cS[tid] = (bin * 7 + genre[p]) * 3 + spk[p];
        sbS[tid] = s_m[m] + s_m[a];
    }
    if (tid < HPAD) {
        float w3v = 0.0f, b2v = 0.0f;
        if (tid < HID) { w3v = W3[tid]; b2v = b2[tid]; }
        W3s[tid] = w3v;
        b2s[tid] = b2v;
    }

    unsigned w_smem_base = (unsigned)__cvta_generic_to_shared(Wb);

    auto stageW2 = [&](int ch, int bsel) {
        unsigned wb = w_smem_base + bsel * (160 * H_STR * 4);
        for (int i4 = tid; i4 < 160 * 4; i4 += 256) {
            int row = i4 >> 2;
            int seg = i4 & 3;
            cpa16(wb + (row * H_STR + seg * 4) * 4,
                  (const char*)d_W2th + row * (KH * 2) + ch * 64 + seg * 16, 16);
        }
    };

    const int kseg = tid & 3;
    const int prb  = tid >> 2;              // 0..63
    auto gather = [&](int ch, int bsel) {
        unsigned* hb = Hb + bsel * (128 * H_STR);
        const int g = ch * 4 + kseg;        // granule 0..19 (16B each)
        #pragma unroll
        for (int it = 0; it < 2; ++it) {
            int p = prb + it * 64;
            const char* ta = (const char*)d_TAh   + (size_t)mS[p] * (ROW_H * 2) + g * 16;
            const char* tb = (const char*)d_TBh   + (size_t)aS[p] * (ROW_H * 2) + g * 16;
            const char* tc = (const char*)d_TPHIh + (size_t)cS[p] * (ROW_H * 2) + g * 16;
            uint4 va = *(const uint4*)ta;
            uint4 vb = *(const uint4*)tb;
            uint4 vc = *(const uint4*)tc;
            uint4 o;
            o.x = h2addrelu(va.x, vb.x, vc.x);
            o.y = h2addrelu(va.y, vb.y, vc.y);
            o.z = h2addrelu(va.z, vb.z, vc.z);
            o.w = h2addrelu(va.w, vb.w, vc.w);
            *(uint4*)(hb + p * H_STR + kseg * 4) = o;
        }
    };

    const int pwarp = (wid & 1) * 64;
    const int jg    = wid >> 1;
    const int jwarp = jg * 40;
    const int lq = lane >> 2;
    const int lr = lane & 3;

    float c[4][5][4];
    #pragma unroll
    for (int pt = 0; pt < 4; ++pt)
        #pragma unroll
        for (int nt = 0; nt < 5; ++nt)
            #pragma unroll
            for (int i = 0; i < 4; ++i) c[pt][nt][i] = 0.0f;

    stageW2(0, 0);
    cpa_commit();
    __syncthreads();                    // metadata visible
    gather(0, 0);

    for (int ch = 0; ch < 5; ++ch) {
        const int buf = ch & 1;
        cpa_wait0();
        __syncthreads();                // H1[buf] + W2[buf] ready
        if (ch < 4) {
            stageW2(ch + 1, buf ^ 1);
            cpa_commit();
            gather(ch + 1, buf ^ 1);
        }
        const unsigned* hb = Hb + buf * (128 * H_STR);
        const unsigned* wb = Wb + buf * (160 * H_STR);
        #pragma unroll
        for (int ks = 0; ks < 2; ++ks) {
            const int kw = ks * 8;
            unsigned bfr[5][2];
            #pragma unroll
            for (int nt = 0; nt < 5; ++nt) {
                int j = jwarp + nt * 8 + lq;
                bfr[nt][0] = wb[j * H_STR + kw + lr];
                bfr[nt][1] = wb[j * H_STR + kw + lr + 4];
            }
            #pragma unroll
            for (int pt = 0; pt < 4; ++pt) {
                int pp = pwarp + pt * 16 + lq;
                unsigned a0 = hb[pp       * H_STR + kw + lr];
                unsigned a1 = hb[(pp + 8) * H_STR + kw + lr];
                unsigned a2 = hb[pp       * H_STR + kw + lr + 4];
                unsigned a3 = hb[(pp + 8) * H_STR + kw + lr + 4];
                #pragma unroll
                for (int nt = 0; nt < 5; ++nt)
                    mma_f16(c[pt][nt][0], c[pt][nt][1], c[pt][nt][2], c[pt][nt][3],
                            a0, a1, a2, a3, bfr[nt][0], bfr[nt][1]);
            }
        }
    }

    // ---- epilogue: relu(+b2) dot W3 ----
    float sp[4][2];
    #pragma unroll
    for (int pt = 0; pt < 4; ++pt) { sp[pt][0] = 0.0f; sp[pt][1] = 0.0f; }

    #pragma unroll
    for (int nt = 0; nt < 5; ++nt) {
        int j = jwarp + nt * 8 + 2 * lr;
        float w3a = W3s[j],     b2a = b2s[j];
        float w3b = W3s[j + 1], b2b = b2s[j + 1];
        #pragma unroll
        for (int pt = 0; pt < 4; ++pt) {
            sp[pt][0] += fmaxf(c[pt][nt][0] + b2a, 0.0f) * w3a;
            sp[pt][0] += fmaxf(c[pt][nt][1] + b2b, 0.0f) * w3b;
            sp[pt][1] += fmaxf(c[pt][nt][2] + b2a, 0.0f) * w3a;
            sp[pt][1] += fmaxf(c[pt][nt][3] + b2b, 0.0f) * w3b;
        }
    }
    #pragma unroll
    for (int pt = 0; pt < 4; ++pt) {
        #pragma unroll
        for (int h = 0; h < 2; ++h) {
            sp[pt][h] += __shfl_xor_sync(0xffffffffu, sp[pt][h], 1);
            sp[pt][h] += __shfl_xor_sync(0xffffffffu, sp[pt][h], 2);
        }
    }

    __syncthreads();   // all buf-1 reads done (last MMA chunk used buf 0)
    if (lr == 0) {
        #pragma unroll
        for (int pt = 0; pt < 4; ++pt) {
            int pp = pwarp + pt * 16 + lq;
            red[jg * 128 + pp]     = sp[pt][0];
            red[jg * 128 + pp + 8] = sp[pt][1];
        }
    }
    __syncthreads();

    if (tid < 128) {
        float t = red[tid] + red[128 + tid] + red[256 + tid] + red[384 + tid];
        out[pbase + tid] = t + b3[0] + sbS[tid];
    }
}

// =====================================================================
// launch
// =====================================================================
extern "C" void kernel_launch(void* const* d_in, const int* in_sizes, int n_in,
                              void* d_out, int out_size)
{
    const float* g    = (const float*)d_in[0];
    const float* s_m  = (const float*)d_in[1];
    const int*   mids = (const int*)d_in[2];
    const int*   aids = (const int*)d_in[3];
    const int*   dist = (const int*)d_in[4];
    const int*   genr = (const int*)d_in[5];
    const int*   spk  = (const int*)d_in[6];
    const float* de   = (const float*)d_in[7];
    const float* ge   = (const float*)d_in[8];
    const float* se   = (const float*)d_in[9];
    const float* W1   = (const float*)d_in[10];
    const float* b1   = (const float*)d_in[11];
    const float* W2   = (const float*)d_in[12];
    const float* b2   = (const float*)d_in[13];
    const float* W3   = (const float*)d_in[14];
    const float* b3   = (const float*)d_in[15];
    float* out = (float*)d_out;

    static int attr_done = 0;
    if (!attr_done) {
        cudaFuncSetAttribute(k_precompute, cudaFuncAttributeMaxDynamicSharedMemorySize, PRE_SMEM_B);
        cudaFuncSetAttribute(k_pairs, cudaFuncAttributeMaxDynamicSharedMemorySize, KP_SMEM_B);
        attr_done = 1;
    }

    k_prepphi<<<PHI_END + 117, 256>>>(W2, de, ge, se, W1, b1);
    k_precompute<<<dim3(16, NSLOTS), 256, PRE_SMEM_B>>>(g);
    k_reduce<<<(N_SPANS * HPAD / 2 + 255) / 256, 256>>>();
    k_pairs<<<NPAIRS / 128, 256, KP_SMEM_B>>>(s_m, mids, aids, dist, genr, spk,
                                              W3, b2, b3, out);
}